// round 10
// baseline (speedup 1.0000x reference)
#include <cuda_runtime.h>
#include <cstdint>

#define HDIM 4096
#define TPB  256
#define V4_PER_THREAD (HDIM / (TPB * 4))   // 4 float4 per thread

__global__ __launch_bounds__(TPB, 8)
void quant_int4_kernel(const float* __restrict__ x,
                       float* __restrict__ packed_out,   // packed int8 VALUES as fp32
                       float* __restrict__ scales_out)
{
    const int row = blockIdx.x;
    const int t   = threadIdx.x;

    const float4* __restrict__ xrow =
        reinterpret_cast<const float4*>(x + (size_t)row * HDIM);

    // ---- pass 1: load 16 elements into registers, local absmax ----
    float4 v[V4_PER_THREAD];
    float amax = 0.0f;
#pragma unroll
    for (int i = 0; i < V4_PER_THREAD; i++) {
        v[i] = xrow[i * TPB + t];
        amax = fmaxf(amax, fmaxf(fmaxf(fabsf(v[i].x), fabsf(v[i].y)),
                                 fmaxf(fabsf(v[i].z), fabsf(v[i].w))));
    }

    // ---- warp reduction ----
#pragma unroll
    for (int o = 16; o > 0; o >>= 1)
        amax = fmaxf(amax, __shfl_xor_sync(0xffffffffu, amax, o));

    // ---- cross-warp reduction (8 warps) ----
    __shared__ float smax[TPB / 32];
    if ((t & 31) == 0) smax[t >> 5] = amax;
    __syncthreads();

    float rmax = smax[0];
#pragma unroll
    for (int w = 1; w < TPB / 32; w++) rmax = fmaxf(rmax, smax[w]);

    const float scale = fmaxf(rmax * (0.9f / 7.0f), 1e-8f);
    const float inv   = 1.0f / scale;

    if (t == 0) scales_out[row] = scale;

    // ---- pass 2: quantize from regs, pack 2 nibbles -> int8 value -> fp32 ----
    float2* __restrict__ orow =
        reinterpret_cast<float2*>(packed_out + (size_t)row * (HDIM / 2));

#pragma unroll
    for (int i = 0; i < V4_PER_THREAD; i++) {
        int q0 = __float2int_rn(v[i].x * inv);
        int q1 = __float2int_rn(v[i].y * inv);
        int q2 = __float2int_rn(v[i].z * inv);
        int q3 = __float2int_rn(v[i].w * inv);
        q0 = max(-8, min(7, q0));
        q1 = max(-8, min(7, q1));
        q2 = max(-8, min(7, q2));
        q3 = max(-8, min(7, q3));
        // elem0 -> low nibble, elem1 -> high nibble; byte is SIGNED int8
        float2 o;
        o.x = (float)(int8_t)(uint8_t)((q0 & 0xF) | ((q1 & 0xF) << 4));
        o.y = (float)(int8_t)(uint8_t)((q2 & 0xF) | ((q3 & 0xF) << 4));
        orow[i * TPB + t] = o;
    }
}

extern "C" void kernel_launch(void* const* d_in, const int* in_sizes, int n_in,
                              void* d_out, int out_size)
{
    const float* x = (const float*)d_in[0];
    const int n_elems = in_sizes[0];              // 4*2048*4096
    const int rows    = n_elems / HDIM;           // 8192

    float* packed = (float*)d_out;                         // [rows, 2048] as fp32
    float* scales = (float*)d_out + (size_t)rows * (HDIM / 2);  // [rows] fp32

    quant_int4_kernel<<<rows, TPB>>>(x, packed, scales);
}

// round 11
// speedup vs baseline: 1.0107x; 1.0107x over previous
#include <cuda_runtime.h>
#include <cstdint>

#define HDIM 4096
#define TPB  512           // two independent 256-thread row-groups per CTA
#define GTH  256           // threads per row-group
#define V4   4             // 4 float4 per thread (16 floats)

__global__ __launch_bounds__(TPB, 4)
void quant_int4_kernel(const float* __restrict__ x,
                       float* __restrict__ packed_out,   // packed int8 VALUES as fp32
                       float* __restrict__ scales_out)
{
    const int t    = threadIdx.x;
    const int wg   = t >> 8;          // row-group 0 or 1
    const int tid  = t & (GTH - 1);   // thread id within group
    const int lane = tid & 31;
    const int warp = tid >> 5;        // 0..7 within group

    const int row  = blockIdx.x * 2 + wg;

    const float4* __restrict__ xrow =
        reinterpret_cast<const float4*>(x + (size_t)row * HDIM);

    // ---- pass 1: 4 x 16B loads per thread (16 floats in regs), absmax ----
    float4 v[V4];
    float amax = 0.0f;
#pragma unroll
    for (int i = 0; i < V4; i++) {
        v[i] = xrow[i * GTH + tid];
        amax = fmaxf(amax, fmaxf(fmaxf(fabsf(v[i].x), fabsf(v[i].y)),
                                 fmaxf(fabsf(v[i].z), fabsf(v[i].w))));
    }

    // ---- warp reduction ----
#pragma unroll
    for (int o = 16; o > 0; o >>= 1)
        amax = fmaxf(amax, __shfl_xor_sync(0xffffffffu, amax, o));

    // ---- cross-warp reduction within the 256-thread group only ----
    __shared__ float smax[2][GTH / 32];
    if (lane == 0) smax[wg][warp] = amax;

    // named barrier per group: groups drift out of phase, keeping DRAM fed
    asm volatile("bar.sync %0, %1;" :: "r"(wg + 1), "n"(GTH) : "memory");

    float rmax = smax[wg][0];
#pragma unroll
    for (int w = 1; w < GTH / 32; w++) rmax = fmaxf(rmax, smax[wg][w]);

    const float scale = fmaxf(rmax * (0.9f / 7.0f), 1e-8f);
    const float inv   = 1.0f / scale;
    if (tid == 0) scales_out[row] = scale;

    // ---- pass 2: quantize from regs, pack 2 nibbles -> int8 value -> fp32 ----
    float2* __restrict__ orow =
        reinterpret_cast<float2*>(packed_out + (size_t)row * (HDIM / 2));

#pragma unroll
    for (int i = 0; i < V4; i++) {
        int q0 = __float2int_rn(v[i].x * inv);
        int q1 = __float2int_rn(v[i].y * inv);
        int q2 = __float2int_rn(v[i].z * inv);
        int q3 = __float2int_rn(v[i].w * inv);
        q0 = max(-8, min(7, q0));
        q1 = max(-8, min(7, q1));
        q2 = max(-8, min(7, q2));
        q3 = max(-8, min(7, q3));
        // elem0 -> low nibble, elem1 -> high nibble; byte is SIGNED int8
        float2 o;
        o.x = (float)(int8_t)(uint8_t)((q0 & 0xF) | ((q1 & 0xF) << 4));
        o.y = (float)(int8_t)(uint8_t)((q2 & 0xF) | ((q3 & 0xF) << 4));
        orow[i * GTH + tid] = o;
    }
}

extern "C" void kernel_launch(void* const* d_in, const int* in_sizes, int n_in,
                              void* d_out, int out_size)
{
    const float* x = (const float*)d_in[0];
    const int n_elems = in_sizes[0];              // 4*2048*4096
    const int rows    = n_elems / HDIM;           // 8192

    float* packed = (float*)d_out;                         // [rows, 2048] as fp32
    float* scales = (float*)d_out + (size_t)rows * (HDIM / 2);  // [rows] fp32

    quant_int4_kernel<<<rows / 2, TPB>>>(x, packed, scales);
}